// round 11
// baseline (speedup 1.0000x reference)
#include <cuda_runtime.h>
#include <cuda_fp16.h>

// BackProjection: B=2, A=180, HR=512, H=W=512, pad=51, Hp=Wp=614
#define A_N   180
#define HR_N  512
#define HOUT  512
#define HP    614
#define PADR  64            // zero-pad rows each side (covers y0 in [-56, 667])
#define HPP   (HP + 2*PADR) // 742 rows per angle

// Zero-padded per-angle column profile in fp16, both batches + next row fused:
// entry.x = half2(b0[y], b1[y]); entry.y = half2(b0[y+1], b1[y+1]),
// with b*[y] == 0 outside [0, HP-1]. One LDG.64 gives a full bilinear-y pair
// for both batches. Zero-initialized (CUDA zero-inits __device__ globals);
// col_kernel writes each value once into row y (.x) and row y-1 (.y).
__device__ uint2 g_colh[A_N * HPP];

__device__ __forceinline__ float2 col_at(const float* __restrict__ sino, int a, int y) {
    float src = ((float)y + 0.5f) * ((float)HR_N / (float)HP) - 0.5f;
    src = fminf(fmaxf(src, 0.0f), (float)(HR_N - 1));
    int i0 = (int)src;                       // src >= 0
    int i1 = min(i0 + 1, HR_N - 1);
    float w = src - (float)i0;
    const float* s0 = sino + a * HR_N;                 // b = 0
    const float* s1 = sino + A_N * HR_N + a * HR_N;    // b = 1
    // match reference rounding: p0*(1-w) + p1*w
    float v0 = s0[i0] * (1.0f - w) + s0[i1] * w;
    float v1 = s1[i0] * (1.0f - w) + s1[i1] * w;
    return make_float2(v0, v1);
}

__global__ void col_kernel(const float* __restrict__ sino) {
    int idx = blockIdx.x * blockDim.x + threadIdx.x;
    if (idx >= A_N * HPP) return;
    int a  = idx / HPP;
    int y  = idx - a * HPP - PADR;          // logical row
    float2 c0 = (y >= 0 && y < HP) ? col_at(sino, a, y) : make_float2(0.f, 0.f);
    __half2 h0 = __floats2half2_rn(c0.x, c0.y);
    unsigned u = *reinterpret_cast<unsigned*>(&h0);
    // row idx: .x = col[y];  row idx-1: .y = col[(y-1)+1] = col[y].
    // Cross-angle boundary (y == -PADR): both the written value and the value
    // the previous angle's last row needs are 0. Last global row's .y is never
    // written and stays zero-init = correct (out-of-range -> 0).
    reinterpret_cast<unsigned*>(&g_colh[idx])[0] = u;
    if (idx > 0)
        reinterpret_cast<unsigned*>(&g_colh[idx - 1])[1] = u;
}

// Packed f32x2 accumulate: acc(.x,.y) += rf(.x,.y) in ONE instruction.
__device__ __forceinline__ void acc_f32x2(float2& acc, float2 rf) {
    unsigned long long* pa = reinterpret_cast<unsigned long long*>(&acc);
    unsigned long long  rb = *reinterpret_cast<unsigned long long*>(&rf);
    asm("add.rn.f32x2 %0, %0, %1;" : "+l"(*pa) : "l"(rb));
}

__global__ __launch_bounds__(128, 8) void bp_kernel(const float* __restrict__ angles,
                                                    float* __restrict__ out) {
    __shared__ float2 sh_cs[A_N];   // (cos, sin) of th = -deg2rad(angle)
    int t = threadIdx.y * 32 + threadIdx.x;
    if (t < A_N) {
        float th = -angles[t] * 0.017453292519943295f;
        sh_cs[t] = make_float2(cosf(th), sinf(th));
    }
    int t2 = t + 128;
    if (t2 < A_N) {
        float th = -angles[t2] * 0.017453292519943295f;
        sh_cs[t2] = make_float2(cosf(th), sinf(th));
    }
    __syncthreads();

    // Each thread handles 2 y-adjacent pixels: (x, y) and (x, y+1).
    // iy(x,y+1) = iy(x,y) + cos, ix(x,y+1) = ix(x,y) - sin  -> trig shared.
    int x = blockIdx.x * 32 + threadIdx.x;
    int y = blockIdx.y * 8 + threadIdx.y * 2;
    float Xp  = (float)x - 255.5f;          // padded coords, center 306.5
    float Yp0 = (float)y - 255.5f;
    float Yp1 = Yp0 + 1.0f;

    float2 acc0 = make_float2(0.f, 0.f);    // pixel (x,y):   (b0, b1)
    float2 acc1 = make_float2(0.f, 0.f);    // pixel (x,y+1): (b0, b1)

    // Interior (both pixels): r^2 < 93500 => ix, iy in (0.5, 612.5) for all
    // angles: no masking, wxe == 1, y0 in [0,612]. Warp-uniform branch.
    bool interior = (fmaf(Xp, Xp, Yp0 * Yp0) < 93500.0f) &
                    (fmaf(Xp, Xp, Yp1 * Yp1) < 93500.0f);

    if (__all_sync(0xffffffffu, interior)) {
        const uint2* __restrict__ colA = g_colh + PADR;
        #pragma unroll 4
        for (int a = 0; a < A_N; ++a, colA += HPP) {
            float2 cs = sh_cs[a];
            float iy0 = fmaf(cs.y, Xp, fmaf(cs.x, Yp0, 306.5f));
            float iy1 = iy0 + cs.x;
            {
                int   q = (int)iy0;                 // iy > 0 -> trunc == floor
                float w = iy0 - (float)q;
                uint2 cc = colA[q];
                __half2 lo = *reinterpret_cast<__half2*>(&cc.x);
                __half2 hi = *reinterpret_cast<__half2*>(&cc.y);
                __half2 r  = __hfma2(__hsub2(hi, lo), __float2half2_rn(w), lo);
                acc_f32x2(acc0, __half22float2(r));
            }
            {
                int   q = (int)iy1;
                float w = iy1 - (float)q;
                uint2 cc = colA[q];
                __half2 lo = *reinterpret_cast<__half2*>(&cc.x);
                __half2 hi = *reinterpret_cast<__half2*>(&cc.y);
                __half2 r  = __hfma2(__hsub2(hi, lo), __float2half2_rn(w), lo);
                acc_f32x2(acc1, __half22float2(r));
            }
        }
    } else {
        // General path. Zero-padded table removes all y masking/clamping;
        // x masking collapses to wxe = clamp(min(ix+1, 614-ix), 0, 1).
        const uint2* __restrict__ colA = g_colh + PADR;
        #pragma unroll 2
        for (int a = 0; a < A_N; ++a, colA += HPP) {
            float2 cs = sh_cs[a];
            float c = cs.x, s = cs.y;
            float ix0 = fmaf(c, Xp, fmaf(-s, Yp0, 306.5f));
            float iy0 = fmaf(s, Xp, fmaf(c, Yp0, 306.5f));
            float ix1 = ix0 - s;
            float iy1 = iy0 + c;
            {
                float wxe = fmaxf(fminf(fminf(ix0 + 1.0f, 614.0f - ix0), 1.0f), 0.0f);
                float qf  = floorf(iy0);
                int   q   = (int)qf;               // in [-56, 667] -> padded range
                float w   = iy0 - qf;
                uint2 cc = colA[q];
                __half2 lo = *reinterpret_cast<__half2*>(&cc.x);
                __half2 hi = *reinterpret_cast<__half2*>(&cc.y);
                __half2 r  = __hfma2(__hsub2(hi, lo), __float2half2_rn(w), lo);
                float2 rf = __half22float2(r);
                acc0.x = fmaf(wxe, rf.x, acc0.x);
                acc0.y = fmaf(wxe, rf.y, acc0.y);
            }
            {
                float wxe = fmaxf(fminf(fminf(ix1 + 1.0f, 614.0f - ix1), 1.0f), 0.0f);
                float qf  = floorf(iy1);
                int   q   = (int)qf;
                float w   = iy1 - qf;
                uint2 cc = colA[q];
                __half2 lo = *reinterpret_cast<__half2*>(&cc.x);
                __half2 hi = *reinterpret_cast<__half2*>(&cc.y);
                __half2 r  = __hfma2(__hsub2(hi, lo), __float2half2_rn(w), lo);
                float2 rf = __half22float2(r);
                acc1.x = fmaf(wxe, rf.x, acc1.x);
                acc1.y = fmaf(wxe, rf.y, acc1.y);
            }
        }
    }

    const float scale = (float)(1.0 / (180.0 + 1e-6));
    int o0 = y * HOUT + x;
    int o1 = o0 + HOUT;
    out[o0]               = acc0.x * scale;
    out[o0 + HOUT * HOUT] = acc0.y * scale;   // batch 1 (out shape (2,1,512,512))
    out[o1]               = acc1.x * scale;
    out[o1 + HOUT * HOUT] = acc1.y * scale;
}

extern "C" void kernel_launch(void* const* d_in, const int* in_sizes, int n_in,
                              void* d_out, int out_size) {
    const float* sino   = (const float*)d_in[0];
    const float* angles = (const float*)d_in[1];
    float* out = (float*)d_out;

    col_kernel<<<(A_N * HPP + 255) / 256, 256>>>(sino);

    dim3 blk(32, 4);                 // 128 threads, 2 pixels each -> 32x8 tile
    dim3 grd(HOUT / 32, HOUT / 8);   // 16 x 64 = 1024 CTAs
    bp_kernel<<<grd, blk>>>(angles, out);
}